// round 8
// baseline (speedup 1.0000x reference)
#include <cuda_runtime.h>

#define D       128
#define N_SRC   200000
#define N_MID   50000
#define N_DST   10000
#define E1      800000
#define E2      160000

typedef unsigned long long u64t;

#define SCAN_CHUNK 2048
#define NB1 ((N_MID + SCAN_CHUNK - 1) / SCAN_CHUNK)   // 25
#define NB2 ((N_DST + SCAN_CHUNK - 1) / SCAN_CHUNK)   // 5

// ---- scratch (static device globals; no runtime allocation) ----
// cnt arrays are zero on module load and re-zeroed at the END of every
// call (invariant across graph replays).
__device__ int   g_cnt1[N_MID + SCAN_CHUNK];
__device__ int   g_off1[NB1 * SCAN_CHUNK];
__device__ int   g_bsum1[32];
__device__ int   g_eidx1[E1];
__device__ int   g_slot1[E1];
__device__ int   g_cnt2[N_DST + SCAN_CHUNK];
__device__ int   g_off2[NB2 * SCAN_CHUNK];
__device__ int   g_bsum2[32];
__device__ int   g_eidx2[E2];
__device__ int   g_slot2[E2];
__device__ float g_agg[N_MID * D];
__device__ float g_h[N_MID * D];
__device__ float g_WT[4 * D * D];     // Wl1^T, Wr1^T, Wl2^T, Wr2^T

// ---------------------------------------------------------------------
__global__ void zero_one(int* c, int n) {
    int i = blockIdx.x * blockDim.x + threadIdx.x;
    if (i < n) c[i] = 0;
}

// Transpose 4 weight matrices (128x128 each) into g_WT.
__global__ void transpose4(const float* __restrict__ W0,
                           const float* __restrict__ W1,
                           const float* __restrict__ W2,
                           const float* __restrict__ W3,
                           float* __restrict__ WT) {
    __shared__ float tile[32][33];
    int m  = blockIdx.x >> 4;         // matrix id 0..3
    int t  = blockIdx.x & 15;         // tile id 0..15
    int tx = (t & 3) * 32;            // tile col base (k)
    int ty = (t >> 2) * 32;           // tile row base (j)
    const float* W = (m == 0) ? W0 : (m == 1) ? W1 : (m == 2) ? W2 : W3;
    int cx = threadIdx.x, cy = threadIdx.y;
    tile[cy][cx] = W[(ty + cy) * D + (tx + cx)];
    __syncthreads();
    WT[(size_t)m * D * D + (tx + cy) * D + (ty + cx)] = tile[cx][cy];
}

// Histogram + slot assignment, 4 edges per thread.
__global__ void hist_slot4(const int* __restrict__ col,
                           int* __restrict__ cnt,
                           int* __restrict__ slot, int E) {
    int b = (blockIdx.x * blockDim.x + threadIdx.x) * 4;
    if (b >= E) return;
    int4 c4 = *(const int4*)(col + b);
    int s0 = atomicAdd(&cnt[c4.x], 1);
    int s1 = atomicAdd(&cnt[c4.y], 1);
    int s2 = atomicAdd(&cnt[c4.z], 1);
    int s3 = atomicAdd(&cnt[c4.w], 1);
    *(int4*)(slot + b) = make_int4(s0, s1, s2, s3);
}

// Per-block scan of SCAN_CHUNK counts.
__global__ void __launch_bounds__(256, 4)
scan_partial(const int* __restrict__ cnt, int* __restrict__ off,
             int* __restrict__ bsum) {
    __shared__ int wsum[8];
    const int t = threadIdx.x, lane = t & 31, w = t >> 5;
    const int base = blockIdx.x * SCAN_CHUNK + t * 8;

    int4 a = *(const int4*)(cnt + base);
    int4 b = *(const int4*)(cnt + base + 4);
    int v[8] = {a.x, a.y, a.z, a.w, b.x, b.y, b.z, b.w};
    int s = 0;
    #pragma unroll
    for (int j = 0; j < 8; j++) s += v[j];

    int x = s;
    #pragma unroll
    for (int d = 1; d < 32; d <<= 1) {
        int y = __shfl_up_sync(0xffffffffu, x, d);
        if (lane >= d) x += y;
    }
    if (lane == 31) wsum[w] = x;
    __syncthreads();
    if (t < 8) {
        int ws = wsum[t];
        int p = 0;
        #pragma unroll
        for (int q = 0; q < 8; q++) {
            int val = __shfl_sync(0xffu, ws, q);
            if (q < t) p += val;
        }
        wsum[t] = p;
    }
    __syncthreads();

    int run = (x - s) + wsum[w];
    int o[8];
    #pragma unroll
    for (int j = 0; j < 8; j++) { o[j] = run; run += v[j]; }
    *(int4*)(off + base)     = make_int4(o[0], o[1], o[2], o[3]);
    *(int4*)(off + base + 4) = make_int4(o[4], o[5], o[6], o[7]);
    if (t == 255) bsum[blockIdx.x] = run;
}

// Per-warp register scan of raw block totals -> lane's exclusive prefix.
__device__ __forceinline__ int warp_bsum_excl(const int* __restrict__ bsum,
                                              int nb) {
    int lane = threadIdx.x & 31;
    int v = (lane < nb) ? bsum[lane] : 0;
    int x = v;
    #pragma unroll
    for (int d = 1; d < 32; d <<= 1) {
        int y = __shfl_up_sync(0xffffffffu, x, d);
        if (lane >= d) x += y;
    }
    return x - v;
}

// Placement, 4 edges/thread, no atomics (tail clamp writes duplicates).
__global__ void place_scatter4(const int* __restrict__ row,
                               const int* __restrict__ col,
                               const int* __restrict__ slot,
                               const int* __restrict__ off,
                               const int* __restrict__ bsum, int nb,
                               int* __restrict__ eidx, int E) {
    int excl = warp_bsum_excl(bsum, nb);
    int b = (blockIdx.x * blockDim.x + threadIdx.x) * 4;
    if (b > E - 4) b = E - 4;
    int4 c4 = *(const int4*)(col + b);
    int4 s4 = *(const int4*)(slot + b);
    int4 r4 = *(const int4*)(row + b);
    int b0 = off[c4.x] + __shfl_sync(0xffffffffu, excl, c4.x >> 11);
    int b1 = off[c4.y] + __shfl_sync(0xffffffffu, excl, c4.y >> 11);
    int b2 = off[c4.z] + __shfl_sync(0xffffffffu, excl, c4.z >> 11);
    int b3 = off[c4.w] + __shfl_sync(0xffffffffu, excl, c4.w >> 11);
    eidx[b0 + s4.x] = r4.x;
    eidx[b1 + s4.y] = r4.y;
    eidx[b2 + s4.z] = r4.z;
    eidx[b3 + s4.w] = r4.w;
}

// ---------------------------------------------------------------------
// Aggregation: one warp per destination row; 4-edge unrolled gather.
// ---------------------------------------------------------------------
__global__ void __launch_bounds__(256)
agg_kernel(const float* __restrict__ xsrc,
           const int* __restrict__ off,
           const int* __restrict__ bsum, int nb,
           const int* __restrict__ eidx,
           float* __restrict__ agg, int n) {
    const int excl = warp_bsum_excl(bsum, nb);
    int c    = (blockIdx.x * blockDim.x + threadIdx.x) >> 5;
    int lane = threadIdx.x & 31;
    if (c >= n) return;
    int s = off[c]     + __shfl_sync(0xffffffffu, excl, c >> 11);
    int e = off[c + 1] + __shfl_sync(0xffffffffu, excl, (c + 1) >> 11);

    float4 acc = make_float4(0.f, 0.f, 0.f, 0.f);
    int i = s;
    for (; i + 4 <= e; i += 4) {
        int r0 = eidx[i + 0], r1 = eidx[i + 1];
        int r2 = eidx[i + 2], r3 = eidx[i + 3];
        float4 v0 = ((const float4*)(xsrc + (size_t)r0 * D))[lane];
        float4 v1 = ((const float4*)(xsrc + (size_t)r1 * D))[lane];
        float4 v2 = ((const float4*)(xsrc + (size_t)r2 * D))[lane];
        float4 v3 = ((const float4*)(xsrc + (size_t)r3 * D))[lane];
        acc.x += (v0.x + v1.x) + (v2.x + v3.x);
        acc.y += (v0.y + v1.y) + (v2.y + v3.y);
        acc.z += (v0.z + v1.z) + (v2.z + v3.z);
        acc.w += (v0.w + v1.w) + (v2.w + v3.w);
    }
    for (; i < e; i++) {
        int r = eidx[i];
        float4 v = ((const float4*)(xsrc + (size_t)r * D))[lane];
        acc.x += v.x; acc.y += v.y; acc.z += v.z; acc.w += v.w;
    }
    float invd = (e > s) ? 1.0f / (float)(e - s) : 0.f;
    acc.x *= invd; acc.y *= invd; acc.z *= invd; acc.w *= invd;
    ((float4*)(agg + (size_t)c * D))[lane] = acc;
}

// ---------------------------------------------------------------------
// SAGE finish, f32x2 FMA, transposed staging, PRE-TRANSPOSED weights
// (straight coalesced smem fill, no bank conflicts, no padding).
// ---------------------------------------------------------------------
#define PADK 10
#define ROWS_PER_BLOCK 64
#define SAGE_SMEM_BYTES ((D * D + D + 8 * D * PADK) * 4)

__device__ __forceinline__ u64t pack2(float a) {
    u64t r;
    unsigned ai = __float_as_uint(a);
    asm("mov.b64 %0, {%1, %1};" : "=l"(r) : "r"(ai));
    return r;
}
__device__ __forceinline__ void ffma2(u64t& d, u64t a, u64t b) {
    asm("fma.rn.f32x2 %0, %1, %2, %3;" : "=l"(d) : "l"(a), "l"(b), "l"(d));
}

template <bool RELU>
__global__ void __launch_bounds__(256, 2)
sage_kernel(const float* __restrict__ agg,
            const float* __restrict__ xdst,
            const float* __restrict__ WTl,   // [k][j] transposed
            const float* __restrict__ bl,
            const float* __restrict__ WTr,   // [k][j] transposed
            float* __restrict__ out, int n) {
    extern __shared__ float smem[];
    float* sW   = smem;                    // D * D (row = k)
    float* sb   = smem + D * D;            // 128
    float* sInT = sb + D;                  // 8 warps * 128 * PADK

    const int tid  = threadIdx.x;
    const int lane = tid & 31;
    const int warp = tid >> 5;
    const int l4   = lane * 4;

    #pragma unroll
    for (int i = 0; i < D * D / 4; i += 256)
        ((float4*)sW)[i + tid] = ((const float4*)WTl)[i + tid];
    if (tid < D) sb[tid] = bl[tid];

    float* myT = sInT + warp * (D * PADK);
    const int rowBase = blockIdx.x * ROWS_PER_BLOCK + warp * 8;

    // ---- stage mean rows transposed: myT[k*PADK + r] ----
    #pragma unroll
    for (int r = 0; r < 8; r++) {
        int row = rowBase + r;
        float4 v = make_float4(0.f, 0.f, 0.f, 0.f);
        if (row < n) v = ((const float4*)(agg + (size_t)row * D))[lane];
        myT[(l4 + 0) * PADK + r] = v.x;
        myT[(l4 + 1) * PADK + r] = v.y;
        myT[(l4 + 2) * PADK + r] = v.z;
        myT[(l4 + 3) * PADK + r] = v.w;
    }
    __syncthreads();

    u64t acc[4][4];
    {
        u64t b0 = pack2(sb[l4 + 0]);
        u64t b1 = pack2(sb[l4 + 1]);
        u64t b2 = pack2(sb[l4 + 2]);
        u64t b3 = pack2(sb[l4 + 3]);
        #pragma unroll
        for (int p = 0; p < 4; p++) {
            acc[p][0] = b0; acc[p][1] = b1; acc[p][2] = b2; acc[p][3] = b3;
        }
    }

    // ---- phase A: mean @ Wl^T ----
    #pragma unroll 4
    for (int k = 0; k < D; k++) {
        float4 w = *(const float4*)&sW[k * D + l4];
        u64t wd0 = pack2(w.x), wd1 = pack2(w.y);
        u64t wd2 = pack2(w.z), wd3 = pack2(w.w);
        const u64t* ak = (const u64t*)&myT[k * PADK];
        u64t a0 = ak[0], a1 = ak[1], a2 = ak[2], a3 = ak[3];
        ffma2(acc[0][0], a0, wd0); ffma2(acc[0][1], a0, wd1);
        ffma2(acc[0][2], a0, wd2); ffma2(acc[0][3], a0, wd3);
        ffma2(acc[1][0], a1, wd0); ffma2(acc[1][1], a1, wd1);
        ffma2(acc[1][2], a1, wd2); ffma2(acc[1][3], a1, wd3);
        ffma2(acc[2][0], a2, wd0); ffma2(acc[2][1], a2, wd1);
        ffma2(acc[2][2], a2, wd2); ffma2(acc[2][3], a2, wd3);
        ffma2(acc[3][0], a3, wd0); ffma2(acc[3][1], a3, wd1);
        ffma2(acc[3][2], a3, wd2); ffma2(acc[3][3], a3, wd3);
    }
    __syncthreads();

    // reload with WTr; restage xdst transposed
    #pragma unroll
    for (int i = 0; i < D * D / 4; i += 256)
        ((float4*)sW)[i + tid] = ((const float4*)WTr)[i + tid];
    #pragma unroll
    for (int r = 0; r < 8; r++) {
        int row = rowBase + r;
        float4 v = make_float4(0.f, 0.f, 0.f, 0.f);
        if (row < n) v = ((const float4*)(xdst + (size_t)row * D))[lane];
        myT[(l4 + 0) * PADK + r] = v.x;
        myT[(l4 + 1) * PADK + r] = v.y;
        myT[(l4 + 2) * PADK + r] = v.z;
        myT[(l4 + 3) * PADK + r] = v.w;
    }
    __syncthreads();

    // ---- phase B: + xdst @ Wr^T ----
    #pragma unroll 4
    for (int k = 0; k < D; k++) {
        float4 w = *(const float4*)&sW[k * D + l4];
        u64t wd0 = pack2(w.x), wd1 = pack2(w.y);
        u64t wd2 = pack2(w.z), wd3 = pack2(w.w);
        const u64t* ak = (const u64t*)&myT[k * PADK];
        u64t a0 = ak[0], a1 = ak[1], a2 = ak[2], a3 = ak[3];
        ffma2(acc[0][0], a0, wd0); ffma2(acc[0][1], a0, wd1);
        ffma2(acc[0][2], a0, wd2); ffma2(acc[0][3], a0, wd3);
        ffma2(acc[1][0], a1, wd0); ffma2(acc[1][1], a1, wd1);
        ffma2(acc[1][2], a1, wd2); ffma2(acc[1][3], a1, wd3);
        ffma2(acc[2][0], a2, wd0); ffma2(acc[2][1], a2, wd1);
        ffma2(acc[2][2], a2, wd2); ffma2(acc[2][3], a2, wd3);
        ffma2(acc[3][0], a3, wd0); ffma2(acc[3][1], a3, wd1);
        ffma2(acc[3][2], a3, wd2); ffma2(acc[3][3], a3, wd3);
    }

    // ---- L2-normalize, (ReLU), store ----
    union F2 { u64t u; float2 f; };
    #pragma unroll
    for (int p = 0; p < 4; p++) {
        F2 c0, c1, c2, c3;
        c0.u = acc[p][0]; c1.u = acc[p][1];
        c2.u = acc[p][2]; c3.u = acc[p][3];
        #pragma unroll
        for (int half = 0; half < 2; half++) {
            int row = rowBase + 2 * p + half;
            float o0 = half ? c0.f.y : c0.f.x;
            float o1 = half ? c1.f.y : c1.f.x;
            float o2 = half ? c2.f.y : c2.f.x;
            float o3 = half ? c3.f.y : c3.f.x;
            float s = o0 * o0 + o1 * o1 + o2 * o2 + o3 * o3;
            #pragma unroll
            for (int d = 16; d > 0; d >>= 1)
                s += __shfl_xor_sync(0xFFFFFFFFu, s, d);
            float inv = 1.0f / fmaxf(sqrtf(s), 1e-12f);
            o0 *= inv; o1 *= inv; o2 *= inv; o3 *= inv;
            if (RELU) {
                o0 = fmaxf(o0, 0.f); o1 = fmaxf(o1, 0.f);
                o2 = fmaxf(o2, 0.f); o3 = fmaxf(o3, 0.f);
            }
            if (row < n)
                ((float4*)(out + (size_t)row * D))[lane] =
                    make_float4(o0, o1, o2, o3);
        }
    }
}

// ---------------------------------------------------------------------
extern "C" void kernel_launch(void* const* d_in, const int* in_sizes, int n_in,
                              void* d_out, int out_size) {
    const float* x    = (const float*)d_in[0];
    const float* Wl1  = (const float*)d_in[1];
    const float* bl1  = (const float*)d_in[2];
    const float* Wr1  = (const float*)d_in[3];
    const float* Wl2  = (const float*)d_in[4];
    const float* bl2  = (const float*)d_in[5];
    const float* Wr2  = (const float*)d_in[6];
    const int*   row1 = (const int*)d_in[7];
    const int*   col1 = (const int*)d_in[8];
    const int*   row2 = (const int*)d_in[9];
    const int*   col2 = (const int*)d_in[10];
    float* out = (float*)d_out;

    int *cnt1, *off1, *bsum1, *eidx1, *slot1;
    int *cnt2, *off2, *bsum2, *eidx2, *slot2;
    float *agg, *h, *WT;
    cudaGetSymbolAddress((void**)&cnt1, g_cnt1);
    cudaGetSymbolAddress((void**)&off1, g_off1);
    cudaGetSymbolAddress((void**)&bsum1, g_bsum1);
    cudaGetSymbolAddress((void**)&eidx1, g_eidx1);
    cudaGetSymbolAddress((void**)&slot1, g_slot1);
    cudaGetSymbolAddress((void**)&cnt2, g_cnt2);
    cudaGetSymbolAddress((void**)&off2, g_off2);
    cudaGetSymbolAddress((void**)&bsum2, g_bsum2);
    cudaGetSymbolAddress((void**)&eidx2, g_eidx2);
    cudaGetSymbolAddress((void**)&slot2, g_slot2);
    cudaGetSymbolAddress((void**)&agg, g_agg);
    cudaGetSymbolAddress((void**)&h,   g_h);
    cudaGetSymbolAddress((void**)&WT,  g_WT);

    cudaFuncSetAttribute(sage_kernel<true>,
                         cudaFuncAttributeMaxDynamicSharedMemorySize, SAGE_SMEM_BYTES);
    cudaFuncSetAttribute(sage_kernel<false>,
                         cudaFuncAttributeMaxDynamicSharedMemorySize, SAGE_SMEM_BYTES);

    static cudaStream_t s_side = nullptr;
    static cudaEvent_t  s_ev0 = nullptr, s_ev1 = nullptr,
                        s_evT = nullptr, s_evA = nullptr, s_evZ = nullptr;
    if (!s_side) {
        cudaStreamCreateWithFlags(&s_side, cudaStreamNonBlocking);
        cudaEventCreateWithFlags(&s_ev0, cudaEventDisableTiming);
        cudaEventCreateWithFlags(&s_ev1, cudaEventDisableTiming);
        cudaEventCreateWithFlags(&s_evT, cudaEventDisableTiming);
        cudaEventCreateWithFlags(&s_evA, cudaEventDisableTiming);
        cudaEventCreateWithFlags(&s_evZ, cudaEventDisableTiming);
    }

    // ---- fork at start: weight transpose + CSR2 on side stream ----
    cudaEventRecord(s_ev0, 0);
    cudaStreamWaitEvent(s_side, s_ev0, 0);
    {
        dim3 tb(32, 32);
        transpose4<<<64, tb, 0, s_side>>>(Wl1, Wr1, Wl2, Wr2, WT);
    }
    cudaEventRecord(s_evT, s_side);   // weights transposed
    hist_slot4<<<(E2 / 4 + 255) / 256, 256, 0, s_side>>>(col2, cnt2, slot2, E2);
    scan_partial<<<NB2, 256, 0, s_side>>>(cnt2, off2, bsum2);
    place_scatter4<<<(E2 / 4 + 255) / 256, 256, 0, s_side>>>(row2, col2, slot2,
                                                             off2, bsum2, NB2,
                                                             eidx2, E2);
    cudaEventRecord(s_ev1, s_side);   // CSR2 ready (join point)

    // ---- main: CSR1 build (cnt1 pre-zeroed by previous call) ----
    hist_slot4<<<(E1 / 4 + 255) / 256, 256>>>(col1, cnt1, slot1, E1);
    scan_partial<<<NB1, 256>>>(cnt1, off1, bsum1);
    cudaEventRecord(s_evA, 0);        // cnt1 fully consumed after scan1
    place_scatter4<<<(E1 / 4 + 255) / 256, 256>>>(row1, col1, slot1,
                                                  off1, bsum1, NB1, eidx1, E1);

    // end-of-call zeroing on side stream (after CSR2 completes there),
    // WAR-guarded against main's cnt1 readers; joined via s_evZ below.
    cudaStreamWaitEvent(s_side, s_evA, 0);
    zero_one<<<(N_MID + SCAN_CHUNK + 255) / 256, 256, 0, s_side>>>(
        cnt1, N_MID + SCAN_CHUNK);
    zero_one<<<(N_DST + SCAN_CHUNK + 255) / 256, 256, 0, s_side>>>(
        cnt2, N_DST + SCAN_CHUNK);
    cudaEventRecord(s_evZ, s_side);   // terminal side-stream event

    // ---- main: layer 1 ----
    agg_kernel<<<(N_MID * 32 + 255) / 256, 256>>>(x, off1, bsum1, NB1,
                                                  eidx1, agg, N_MID);
    cudaStreamWaitEvent(0, s_evT, 0);   // need transposed weights
    sage_kernel<true><<<(N_MID + ROWS_PER_BLOCK - 1) / ROWS_PER_BLOCK, 256,
                        SAGE_SMEM_BYTES>>>(agg, x, WT + 0 * D * D, bl1,
                                           WT + 1 * D * D, h, N_MID);

    // ---- join, layer 2 ----
    cudaStreamWaitEvent(0, s_ev1, 0);
    agg_kernel<<<(N_DST * 32 + 255) / 256, 256>>>(h, off2, bsum2, NB2,
                                                  eidx2, agg, N_DST);
    sage_kernel<false><<<(N_DST + ROWS_PER_BLOCK - 1) / ROWS_PER_BLOCK, 256,
                         SAGE_SMEM_BYTES>>>(agg, h, WT + 2 * D * D, bl2,
                                            WT + 3 * D * D, out, N_DST);

    // join the side stream's trailing zero kernels into the capture DAG
    cudaStreamWaitEvent(0, s_evZ, 0);
}

// round 9
// speedup vs baseline: 1.3706x; 1.3706x over previous
#include <cuda_runtime.h>

#define D       128
#define N_SRC   200000
#define N_MID   50000
#define N_DST   10000
#define E1      800000
#define E2      160000

typedef unsigned long long u64t;

#define SCAN_CHUNK 2048
#define NB1 ((N_MID + SCAN_CHUNK - 1) / SCAN_CHUNK)   // 25
#define NB2 ((N_DST + SCAN_CHUNK - 1) / SCAN_CHUNK)   // 5

// ---- scratch (static device globals; no runtime allocation) ----
__device__ int   g_cnt1[N_MID + SCAN_CHUNK];
__device__ int   g_off1[NB1 * SCAN_CHUNK];
__device__ int   g_bsum1[32];                 // RAW per-block totals
__device__ int   g_eidx1[E1];
__device__ int   g_slot1[E1];
__device__ int   g_cnt2[N_DST + SCAN_CHUNK];
__device__ int   g_off2[NB2 * SCAN_CHUNK];
__device__ int   g_bsum2[32];
__device__ int   g_eidx2[E2];
__device__ int   g_slot2[E2];
__device__ float g_agg[N_MID * D];
__device__ float g_h[N_MID * D];

// ---------------------------------------------------------------------
// Zero both (padded) count arrays in one launch (R3 structure).
// ---------------------------------------------------------------------
__global__ void zero_all(int* c1, int n1, int* c2, int n2) {
    int i = blockIdx.x * blockDim.x + threadIdx.x;
    if (i < n1) c1[i] = 0;
    if (i < n2) c2[i] = 0;
}

// Histogram + slot assignment in one pass (1 edge/thread — proven fastest).
__global__ void hist_slot(const int* __restrict__ col,
                          int* __restrict__ cnt,
                          int* __restrict__ slot, int E) {
    int i = blockIdx.x * blockDim.x + threadIdx.x;
    if (i < E) slot[i] = atomicAdd(&cnt[col[i]], 1);
}

// Per-block scan of SCAN_CHUNK counts; off[] gets within-block EXCLUSIVE
// prefixes, bsum[b] gets the RAW block total (no second-stage kernel).
__global__ void __launch_bounds__(256, 4)
scan_partial(const int* __restrict__ cnt, int* __restrict__ off,
             int* __restrict__ bsum) {
    __shared__ int wsum[8];
    const int t = threadIdx.x, lane = t & 31, w = t >> 5;
    const int base = blockIdx.x * SCAN_CHUNK + t * 8;

    int4 a = *(const int4*)(cnt + base);
    int4 b = *(const int4*)(cnt + base + 4);
    int v[8] = {a.x, a.y, a.z, a.w, b.x, b.y, b.z, b.w};
    int s = 0;
    #pragma unroll
    for (int j = 0; j < 8; j++) s += v[j];

    int x = s;
    #pragma unroll
    for (int d = 1; d < 32; d <<= 1) {
        int y = __shfl_up_sync(0xffffffffu, x, d);
        if (lane >= d) x += y;
    }
    if (lane == 31) wsum[w] = x;
    __syncthreads();
    if (t < 8) {
        int ws = wsum[t];
        int p = 0;
        #pragma unroll
        for (int q = 0; q < 8; q++) {
            int val = __shfl_sync(0xffu, ws, q);
            if (q < t) p += val;
        }
        wsum[t] = p;
    }
    __syncthreads();

    int run = (x - s) + wsum[w];
    int o[8];
    #pragma unroll
    for (int j = 0; j < 8; j++) { o[j] = run; run += v[j]; }
    *(int4*)(off + base)     = make_int4(o[0], o[1], o[2], o[3]);
    *(int4*)(off + base + 4) = make_int4(o[4], o[5], o[6], o[7]);
    if (t == 255) bsum[blockIdx.x] = run;
}

// Per-warp register scan of raw block totals -> lane's exclusive prefix.
// (Replaces the standalone scan_bsums kernel.)
__device__ __forceinline__ int warp_bsum_excl(const int* __restrict__ bsum,
                                              int nb) {
    int lane = threadIdx.x & 31;
    int v = (lane < nb) ? bsum[lane] : 0;
    int x = v;
    #pragma unroll
    for (int d = 1; d < 32; d <<= 1) {
        int y = __shfl_up_sync(0xffffffffu, x, d);
        if (lane >= d) x += y;
    }
    return x - v;
}

// Placement: pure scatter, 1 edge/thread, no atomics.
__global__ void place_scatter(const int* __restrict__ row,
                              const int* __restrict__ col,
                              const int* __restrict__ slot,
                              const int* __restrict__ off,
                              const int* __restrict__ bsum, int nb,
                              int* __restrict__ eidx, int E) {
    int excl = warp_bsum_excl(bsum, nb);
    int i = blockIdx.x * blockDim.x + threadIdx.x;
    if (i < E) {
        int c = col[i];
        int base = off[c] + __shfl_sync(0xffffffffu, excl, c >> 11);
        eidx[base + slot[i]] = row[i];
    }
}

// ---------------------------------------------------------------------
// Aggregation: one warp per destination row; 4-edge unrolled gather.
// ---------------------------------------------------------------------
__global__ void __launch_bounds__(256)
agg_kernel(const float* __restrict__ xsrc,
           const int* __restrict__ off,
           const int* __restrict__ bsum, int nb,
           const int* __restrict__ eidx,
           float* __restrict__ agg, int n) {
    const int excl = warp_bsum_excl(bsum, nb);
    int c    = (blockIdx.x * blockDim.x + threadIdx.x) >> 5;
    int lane = threadIdx.x & 31;
    if (c >= n) return;
    int s = off[c]     + __shfl_sync(0xffffffffu, excl, c >> 11);
    int e = off[c + 1] + __shfl_sync(0xffffffffu, excl, (c + 1) >> 11);

    float4 acc = make_float4(0.f, 0.f, 0.f, 0.f);
    int i = s;
    for (; i + 4 <= e; i += 4) {
        int r0 = eidx[i + 0], r1 = eidx[i + 1];
        int r2 = eidx[i + 2], r3 = eidx[i + 3];
        float4 v0 = ((const float4*)(xsrc + (size_t)r0 * D))[lane];
        float4 v1 = ((const float4*)(xsrc + (size_t)r1 * D))[lane];
        float4 v2 = ((const float4*)(xsrc + (size_t)r2 * D))[lane];
        float4 v3 = ((const float4*)(xsrc + (size_t)r3 * D))[lane];
        acc.x += (v0.x + v1.x) + (v2.x + v3.x);
        acc.y += (v0.y + v1.y) + (v2.y + v3.y);
        acc.z += (v0.z + v1.z) + (v2.z + v3.z);
        acc.w += (v0.w + v1.w) + (v2.w + v3.w);
    }
    for (; i < e; i++) {
        int r = eidx[i];
        float4 v = ((const float4*)(xsrc + (size_t)r * D))[lane];
        acc.x += v.x; acc.y += v.y; acc.z += v.z; acc.w += v.w;
    }
    float invd = (e > s) ? 1.0f / (float)(e - s) : 0.f;
    acc.x *= invd; acc.y *= invd; acc.z *= invd; acc.w *= invd;
    ((float4*)(agg + (size_t)c * D))[lane] = acc;
}

// ---------------------------------------------------------------------
// SAGE finish with f32x2 FMA (R3-proven version). ONE weight buffer in
// SMEM at a time -> ~101 KB smem -> 2 blocks/SM.
// ---------------------------------------------------------------------
#define KS 132
#define RPW 8
#define ROWS_PER_BLOCK 64
#define SAGE_SMEM_BYTES ((KS * D + D + ROWS_PER_BLOCK * D) * 4)

__device__ __forceinline__ u64t pack2(float a) {
    u64t r;
    unsigned ai = __float_as_uint(a);
    asm("mov.b64 %0, {%1, %1};" : "=l"(r) : "r"(ai));
    return r;
}
__device__ __forceinline__ void ffma2(u64t& d, u64t a, u64t b) {
    asm("fma.rn.f32x2 %0, %1, %2, %3;" : "=l"(d) : "l"(a), "l"(b), "l"(d));
}

template <bool RELU>
__global__ void __launch_bounds__(256, 2)
sage_kernel(const float* __restrict__ agg,
            const float* __restrict__ xdst,
            const float* __restrict__ Wl, const float* __restrict__ bl,
            const float* __restrict__ Wr,
            float* __restrict__ out, int n) {
    extern __shared__ float smem[];
    float* sW  = smem;                    // KS * 128 transposed (reused)
    float* sb  = smem + KS * D;           // 128
    float* sIn = sb + D;                  // 64 * 128 staging

    const int tid  = threadIdx.x;
    const int lane = tid & 31;
    const int warp = tid >> 5;
    const int l4   = lane * 4;

    // load Wl transposed + bias
    for (int idx = tid; idx < D * D; idx += 256) {
        int j = idx >> 7, k = idx & (D - 1);
        sW[k * KS + j] = Wl[idx];
    }
    if (tid < D) sb[tid] = bl[tid];

    float* myIn = sIn + warp * (RPW * D);
    const int rowBase = blockIdx.x * ROWS_PER_BLOCK + warp * RPW;

    // stage mean rows
    #pragma unroll
    for (int r = 0; r < RPW; r++) {
        int row = rowBase + r;
        float4 v = make_float4(0.f, 0.f, 0.f, 0.f);
        if (row < n) v = ((const float4*)(agg + (size_t)row * D))[lane];
        ((float4*)(myIn + r * D))[lane] = v;
    }
    __syncthreads();

    u64t acc[RPW][2];
    {
        u64t b0 = *(const u64t*)&sb[l4];
        u64t b1 = *(const u64t*)&sb[l4 + 2];
        #pragma unroll
        for (int r = 0; r < RPW; r++) { acc[r][0] = b0; acc[r][1] = b1; }
    }

    // ---- phase A: mean @ Wl^T ----
    #pragma unroll 4
    for (int k = 0; k < D; k++) {
        ulonglong2 w = *(const ulonglong2*)&sW[k * KS + l4];
        #pragma unroll
        for (int r = 0; r < RPW; r++) {
            u64t a = pack2(myIn[r * D + k]);
            ffma2(acc[r][0], a, w.x);
            ffma2(acc[r][1], a, w.y);
        }
    }
    __syncthreads();   // done reading Wl + mean staging

    // reload buffer with Wr; restage xdst
    for (int idx = tid; idx < D * D; idx += 256) {
        int j = idx >> 7, k = idx & (D - 1);
        sW[k * KS + j] = Wr[idx];
    }
    #pragma unroll
    for (int r = 0; r < RPW; r++) {
        int row = rowBase + r;
        float4 v = make_float4(0.f, 0.f, 0.f, 0.f);
        if (row < n) v = ((const float4*)(xdst + (size_t)row * D))[lane];
        ((float4*)(myIn + r * D))[lane] = v;
    }
    __syncthreads();

    // ---- phase B: + xdst @ Wr^T ----
    #pragma unroll 4
    for (int k = 0; k < D; k++) {
        ulonglong2 w = *(const ulonglong2*)&sW[k * KS + l4];
        #pragma unroll
        for (int r = 0; r < RPW; r++) {
            u64t a = pack2(myIn[r * D + k]);
            ffma2(acc[r][0], a, w.x);
            ffma2(acc[r][1], a, w.y);
        }
    }

    // ---- L2-normalize, (ReLU), store ----
    union F2 { u64t u; float2 f; };
    #pragma unroll
    for (int r = 0; r < RPW; r++) {
        int row = rowBase + r;
        F2 a0, a1; a0.u = acc[r][0]; a1.u = acc[r][1];
        float o0 = a0.f.x, o1 = a0.f.y, o2 = a1.f.x, o3 = a1.f.y;
        float s = o0 * o0 + o1 * o1 + o2 * o2 + o3 * o3;
        #pragma unroll
        for (int d = 16; d > 0; d >>= 1)
            s += __shfl_xor_sync(0xFFFFFFFFu, s, d);
        float inv = 1.0f / fmaxf(sqrtf(s), 1e-12f);
        o0 *= inv; o1 *= inv; o2 *= inv; o3 *= inv;
        if (RELU) {
            o0 = fmaxf(o0, 0.f); o1 = fmaxf(o1, 0.f);
            o2 = fmaxf(o2, 0.f); o3 = fmaxf(o3, 0.f);
        }
        if (row < n)
            ((float4*)(out + (size_t)row * D))[lane] = make_float4(o0, o1, o2, o3);
    }
}

// ---------------------------------------------------------------------
// Launch sequence — EXACT R3 structure (zero_all up front, fork CSR2 at
// start on normal-priority side stream, single join), minus the two
// scan_bsums launches (folded into consumers).
// ---------------------------------------------------------------------
extern "C" void kernel_launch(void* const* d_in, const int* in_sizes, int n_in,
                              void* d_out, int out_size) {
    const float* x    = (const float*)d_in[0];
    const float* Wl1  = (const float*)d_in[1];
    const float* bl1  = (const float*)d_in[2];
    const float* Wr1  = (const float*)d_in[3];
    const float* Wl2  = (const float*)d_in[4];
    const float* bl2  = (const float*)d_in[5];
    const float* Wr2  = (const float*)d_in[6];
    const int*   row1 = (const int*)d_in[7];
    const int*   col1 = (const int*)d_in[8];
    const int*   row2 = (const int*)d_in[9];
    const int*   col2 = (const int*)d_in[10];
    float* out = (float*)d_out;

    int *cnt1, *off1, *bsum1, *eidx1, *slot1;
    int *cnt2, *off2, *bsum2, *eidx2, *slot2;
    float *agg, *h;
    cudaGetSymbolAddress((void**)&cnt1, g_cnt1);
    cudaGetSymbolAddress((void**)&off1, g_off1);
    cudaGetSymbolAddress((void**)&bsum1, g_bsum1);
    cudaGetSymbolAddress((void**)&eidx1, g_eidx1);
    cudaGetSymbolAddress((void**)&slot1, g_slot1);
    cudaGetSymbolAddress((void**)&cnt2, g_cnt2);
    cudaGetSymbolAddress((void**)&off2, g_off2);
    cudaGetSymbolAddress((void**)&bsum2, g_bsum2);
    cudaGetSymbolAddress((void**)&eidx2, g_eidx2);
    cudaGetSymbolAddress((void**)&slot2, g_slot2);
    cudaGetSymbolAddress((void**)&agg, g_agg);
    cudaGetSymbolAddress((void**)&h,   g_h);

    cudaFuncSetAttribute(sage_kernel<true>,
                         cudaFuncAttributeMaxDynamicSharedMemorySize, SAGE_SMEM_BYTES);
    cudaFuncSetAttribute(sage_kernel<false>,
                         cudaFuncAttributeMaxDynamicSharedMemorySize, SAGE_SMEM_BYTES);

    static cudaStream_t s_side = nullptr;
    static cudaEvent_t  s_ev0  = nullptr, s_ev1 = nullptr;
    if (!s_side) {
        cudaStreamCreateWithFlags(&s_side, cudaStreamNonBlocking);
        cudaEventCreateWithFlags(&s_ev0, cudaEventDisableTiming);
        cudaEventCreateWithFlags(&s_ev1, cudaEventDisableTiming);
    }

    // zero both count arrays (padded) in one kernel (main stream)
    {
        int nmax = N_MID + SCAN_CHUNK;
        zero_all<<<(nmax + 255) / 256, 256>>>(cnt1, N_MID + SCAN_CHUNK,
                                              cnt2, N_DST + SCAN_CHUNK);
    }

    // ---- fork: CSR2 build on side stream ----
    cudaEventRecord(s_ev0, 0);
    cudaStreamWaitEvent(s_side, s_ev0, 0);
    hist_slot<<<(E2 + 255) / 256, 256, 0, s_side>>>(col2, cnt2, slot2, E2);
    scan_partial<<<NB2, 256, 0, s_side>>>(cnt2, off2, bsum2);
    place_scatter<<<(E2 + 255) / 256, 256, 0, s_side>>>(row2, col2, slot2,
                                                        off2, bsum2, NB2,
                                                        eidx2, E2);
    cudaEventRecord(s_ev1, s_side);

    // ---- main: CSR1 build + layer 1 ----
    hist_slot<<<(E1 + 255) / 256, 256>>>(col1, cnt1, slot1, E1);
    scan_partial<<<NB1, 256>>>(cnt1, off1, bsum1);
    place_scatter<<<(E1 + 255) / 256, 256>>>(row1, col1, slot1,
                                             off1, bsum1, NB1, eidx1, E1);
    agg_kernel<<<(N_MID * 32 + 255) / 256, 256>>>(x, off1, bsum1, NB1,
                                                  eidx1, agg, N_MID);
    sage_kernel<true><<<(N_MID + ROWS_PER_BLOCK - 1) / ROWS_PER_BLOCK, 256,
                        SAGE_SMEM_BYTES>>>(agg, x, Wl1, bl1, Wr1, h, N_MID);

    // ---- join, layer 2 ----
    cudaStreamWaitEvent(0, s_ev1, 0);
    agg_kernel<<<(N_DST * 32 + 255) / 256, 256>>>(h, off2, bsum2, NB2,
                                                  eidx2, agg, N_DST);
    sage_kernel<false><<<(N_DST + ROWS_PER_BLOCK - 1) / ROWS_PER_BLOCK, 256,
                         SAGE_SMEM_BYTES>>>(agg, h, Wl2, bl2, Wr2, out, N_DST);
}